// round 16
// baseline (speedup 1.0000x reference)
#include <cuda_runtime.h>
#include <cuda_fp16.h>
#include <mma.h>
#include <cstdio>
#include <cstdlib>
#include <cmath>

using namespace nvcuda;

#define NN 50000
#define EE 800000
#define E2 850000   // EE + NN self loops
#define EMB 128
#define LL 2
#define BB 8

// ---------------- scratch (no cudaMalloc allowed) ----------------
// NOTE: host code must NEVER pass these symbols as kernel args directly —
// always cudaGetSymbolAddress (R6 root cause).
__device__ __align__(16) float g_h[NN * EMB];
__device__ __align__(16) unsigned int g_xsh[NN * 64];     // xs as half2 pairs (only consumer: nodeagg)
__device__ __align__(16) float g_tmp[NN * EMB];
__device__ __align__(16) float g_as[NN * 4];
__device__ __align__(16) float g_ad[NN * 4];
__device__ __align__(16) float g_alpha[(size_t)E2 * 4];   // exp(alpha), CSR order
__device__ int   g_deg[NN];
__device__ int   g_rowptr[NN + 1];
__device__ int   g_wpos[NN];
__device__ int   g_csr[E2];
__device__ int   g_csrsrc[E2];
__device__ int   g_csrdst[E2];
__device__ float g_part[128 * 16];
__device__ float g_M2[LL][64];      // per-layer [16][4]
__device__ float g_aeloop2[LL][4];
__device__ int   g_bstart[BB + 1];

__device__ __forceinline__ float wredsum(float v) {
#pragma unroll
    for (int o = 16; o; o >>= 1) v += __shfl_xor_sync(0xffffffffu, v, o);
    return v;
}
__device__ __forceinline__ int iclamp(int v, int lo, int hi) {
    return v < lo ? lo : (v > hi ? hi : v);
}

// ---------------- setup_a: emean partials (blocks 0..127) + zero_deg (blocks 128+) ----
__global__ void setup_a_k(const float* __restrict__ ea) {
    if (blockIdx.x >= 128) {
        int i = (blockIdx.x - 128) * blockDim.x + threadIdx.x;
        if (i < NN) g_deg[i] = 0;
        return;
    }
    float acc[16];
#pragma unroll
    for (int k = 0; k < 16; k++) acc[k] = 0.f;
    for (int e = blockIdx.x * blockDim.x + threadIdx.x; e < EE; e += 128 * blockDim.x) {
        const float4* p = (const float4*)(ea + (size_t)e * 16);
#pragma unroll
        for (int q = 0; q < 4; q++) {
            float4 v = p[q];
            acc[q * 4 + 0] += v.x; acc[q * 4 + 1] += v.y;
            acc[q * 4 + 2] += v.z; acc[q * 4 + 3] += v.w;
        }
    }
    __shared__ float sh[256 * 16];
    int t = threadIdx.x;
#pragma unroll
    for (int k = 0; k < 16; k++) sh[t * 16 + k] = acc[k];
    __syncthreads();
    for (int off = 128; off; off >>= 1) {
        if (t < off)
#pragma unroll
            for (int k = 0; k < 16; k++) sh[t * 16 + k] += sh[(t + off) * 16 + k];
        __syncthreads();
    }
    if (t < 16) g_part[blockIdx.x * 16 + t] = sh[t];
}

// ---------------- setup_b: block 0 = emean2 + prepM(both layers); blocks 1+ = bounds --
__global__ void setup_b_k(const float* __restrict__ W_edge,
                          const float* __restrict__ att_edge,
                          const int* __restrict__ batch) {
    if (blockIdx.x > 0) {
        int n = (blockIdx.x - 1) * blockDim.x + threadIdx.x;
        if (n >= NN) return;
        int b = iclamp(batch[n], 0, BB - 1);
        if (n == 0) {
            for (int bb = 0; bb <= b; bb++) g_bstart[bb] = 0;
        } else {
            int bp = iclamp(batch[n - 1], 0, BB - 1);
            for (int bb = bp + 1; bb <= b; bb++) g_bstart[bb] = n;
        }
        if (n == NN - 1) {
            for (int bb = b + 1; bb <= BB; bb++) g_bstart[bb] = NN;
        }
        return;
    }
    __shared__ float sem[16];
    __shared__ float sM[LL][64];
    int t = threadIdx.x;
    if (t < 16) {
        float s = 0.f;
        for (int b = 0; b < 128; b++) s += g_part[b * 16 + t];
        sem[t] = s * (1.f / (float)EE);
    }
    __syncthreads();
    if (t < 128) {
        int l = t >> 6, kk = (t & 63) >> 2, h = t & 3;
        const float* We = W_edge + l * 16 * EMB;
        const float* ae = att_edge + l * EMB;
        float s = 0.f;
#pragma unroll
        for (int c = 0; c < 32; c++) s += We[kk * 128 + h * 32 + c] * ae[h * 32 + c];
        sM[l][kk * 4 + h] = s;
        g_M2[l][kk * 4 + h] = s;
    }
    __syncthreads();
    if (t < 8) {
        int l = t >> 2, h = t & 3;
        float s = 0.f;
        for (int k = 0; k < 16; k++) s += sem[k] * sM[l][k * 4 + h];
        g_aeloop2[l][h] = s;
    }
}

__global__ void hist_k(const int* __restrict__ ei) {
    int e = blockIdx.x * blockDim.x + threadIdx.x;
    if (e >= E2) return;
    int dst = (e < EE) ? ei[EE + e] : (e - EE);
    dst = iclamp(dst, 0, NN - 1);
    atomicAdd(&g_deg[dst], 1);
}

__global__ void scan_k() {
    const int T = 1024;
    __shared__ int wsum[32];
    __shared__ int carry;
    int t = threadIdx.x, lane = t & 31, w = t >> 5;
    if (t == 0) carry = 0;
    __syncthreads();
    for (int base = 0; base < NN; base += T) {
        int i = base + t;
        int v = (i < NN) ? g_deg[i] : 0;
        int x = v;
#pragma unroll
        for (int o = 1; o < 32; o <<= 1) {
            int y = __shfl_up_sync(0xffffffffu, x, o);
            if (lane >= o) x += y;
        }
        if (lane == 31) wsum[w] = x;
        __syncthreads();
        if (w == 0) {
            int y = wsum[lane];
#pragma unroll
            for (int o = 1; o < 32; o <<= 1) {
                int z = __shfl_up_sync(0xffffffffu, y, o);
                if (lane >= o) y += z;
            }
            wsum[lane] = y;
        }
        __syncthreads();
        int pre = (w > 0) ? wsum[w - 1] : 0;
        int excl = carry + pre + x - v;
        if (i < NN) { g_rowptr[i] = excl; g_wpos[i] = excl; }
        int total = wsum[31];
        __syncthreads();
        if (t == 0) carry += total;
        __syncthreads();
    }
    if (t == 0) g_rowptr[NN] = carry;
}

__global__ void scatter_k(const int* __restrict__ ei) {
    int e = blockIdx.x * blockDim.x + threadIdx.x;
    if (e >= E2) return;
    int src, dst;
    if (e < EE) { src = ei[e]; dst = ei[EE + e]; }
    else        { src = dst = e - EE; }
    src = iclamp(src, 0, NN - 1);
    dst = iclamp(dst, 0, NN - 1);
    int p = atomicAdd(&g_wpos[dst], 1);
    p = iclamp(p, 0, E2 - 1);
    g_csr[p] = e;
    g_csrsrc[p] = src;
    g_csrdst[p] = dst;
}

// ---------------- TF32 tensor-core GEMM, BM=64, software-pipelined staging ----
// (R14 mainloop — validated 63.6us @ K=160; mainloop untouched)
// EPI: 0 = store fp32 (+bias/relu); 1 = store HALF2 to Ch + a_s/a_d dots;
//      2 = bias+relu+LayerNorm fp32
template <int K0, int K1, bool RELU, int EPI>
__global__ __launch_bounds__(256, 3) void gemmtc_k(
    const float* __restrict__ A0, const float* __restrict__ A1,
    const float* __restrict__ W, const float* __restrict__ bias,
    float* __restrict__ C, int nrows,
    const float* __restrict__ asrc, const float* __restrict__ adst,
    float* __restrict__ pas, float* __restrict__ pad,
    const float* __restrict__ gamma, const float* __restrict__ beta,
    unsigned int* __restrict__ Ch)
{
    constexpr int K = K0 + K1;
    constexpr int KC = 32;
    constexpr int NCH = (K + KC - 1) / KC;
    constexpr int ALD = KC + 8;    // 40
    constexpr int WLD = 128 + 8;   // 136
    constexpr int CLD = 128 + 4;   // 132

    __shared__ union {
        struct { float As[64][ALD]; float Ws[KC][WLD]; } L;
        float Cs[64][CLD];
    } sm;

    int t = threadIdx.x;
    int warp = t >> 5;
    int lane = t & 31;
    int wr = warp >> 1;   // 0..3
    int wc = warp & 1;    // 0..1
    int row0 = blockIdx.x * 64;

    int ra = t >> 5;         // A base row
    int ka = t & 31;         // A k-column
    int kw = t >> 7;         // W base k
    int jw = t & 127;        // W column

    float rAv[8];
    float rWv[16];

    wmma::fragment<wmma::accumulator, 16, 16, 8, float> acc[4];
#pragma unroll
    for (int j = 0; j < 4; j++) wmma::fill_fragment(acc[j], 0.f);

    {
        int gk = ka;
#pragma unroll
        for (int i = 0; i < 8; i++) {
            int gr = row0 + ra + i * 8;
            float v = 0.f;
            if (gr < nrows && gk < K) {
                if (K1 == 0 || gk < K0) v = A0[(size_t)gr * K0 + gk];
                else                    v = A1[(size_t)gr * K1 + (gk - K0)];
            }
            rAv[i] = v;
        }
#pragma unroll
        for (int i = 0; i < 16; i++) {
            int k = kw + i * 2;
            float v = (k < K) ? W[(size_t)k * 128 + jw] : 0.f;
            rWv[i] = v;
        }
    }

    for (int ch = 0; ch < NCH; ch++) {
#pragma unroll
        for (int i = 0; i < 8; i++)
            sm.L.As[ra + i * 8][ka] = wmma::__float_to_tf32(rAv[i]);
#pragma unroll
        for (int i = 0; i < 16; i++)
            sm.L.Ws[kw + i * 2][jw] = wmma::__float_to_tf32(rWv[i]);
        __syncthreads();

        if (ch + 1 < NCH) {
            int gkb = (ch + 1) * KC;
            int gk = gkb + ka;
#pragma unroll
            for (int i = 0; i < 8; i++) {
                int gr = row0 + ra + i * 8;
                float v = 0.f;
                if (gr < nrows && gk < K) {
                    if (K1 == 0 || gk < K0) v = A0[(size_t)gr * K0 + gk];
                    else                    v = A1[(size_t)gr * K1 + (gk - K0)];
                }
                rAv[i] = v;
            }
#pragma unroll
            for (int i = 0; i < 16; i++) {
                int k = gkb + kw + i * 2;
                float v = (k < K) ? W[(size_t)k * 128 + jw] : 0.f;
                rWv[i] = v;
            }
        }

#pragma unroll
        for (int ks = 0; ks < KC; ks += 8) {
            wmma::fragment<wmma::matrix_a, 16, 16, 8, wmma::precision::tf32,
                           wmma::row_major> fa;
            wmma::load_matrix_sync(fa, &sm.L.As[wr * 16][ks], ALD);
#pragma unroll
            for (int j = 0; j < 4; j++) {
                wmma::fragment<wmma::matrix_b, 16, 16, 8, wmma::precision::tf32,
                               wmma::row_major> fb;
                wmma::load_matrix_sync(fb, &sm.L.Ws[ks][wc * 64 + j * 16], WLD);
                wmma::mma_sync(acc[j], fa, fb, acc[j]);
            }
        }
        __syncthreads();
    }

#pragma unroll
    for (int j = 0; j < 4; j++)
        wmma::store_matrix_sync(&sm.Cs[wr * 16][wc * 64 + j * 16], acc[j], CLD,
                                wmma::mem_row_major);
    __syncthreads();

    if (EPI == 2) {
#pragma unroll 1
        for (int rr = 0; rr < 8; rr++) {
            int row = warp * 8 + rr;
            int gr = row0 + row;
            if (gr >= nrows) continue;
            float4 v = *(const float4*)&sm.Cs[row][lane * 4];
            float4 bb = ((const float4*)bias)[lane];
            v.x += bb.x; v.y += bb.y; v.z += bb.z; v.w += bb.w;
            if (RELU) {
                v.x = fmaxf(v.x, 0.f); v.y = fmaxf(v.y, 0.f);
                v.z = fmaxf(v.z, 0.f); v.w = fmaxf(v.w, 0.f);
            }
            float s = wredsum(v.x + v.y + v.z + v.w);
            float mean = s * (1.f / 128.f);
            float dx = v.x - mean, dy = v.y - mean, dz = v.z - mean, dw = v.w - mean;
            float q = wredsum(dx * dx + dy * dy + dz * dz + dw * dw);
            float rstd = rsqrtf(q * (1.f / 128.f) + 1e-5f);
            float4 gg = ((const float4*)gamma)[lane];
            float4 be = ((const float4*)beta)[lane];
            float4 r;
            r.x = dx * rstd * gg.x + be.x;
            r.y = dy * rstd * gg.y + be.y;
            r.z = dz * rstd * gg.z + be.z;
            r.w = dw * rstd * gg.w + be.w;
            ((float4*)C)[(size_t)gr * 32 + lane] = r;
        }
    } else if (EPI == 1) {
        // store xs as half2 pairs only (sole consumer: nodeagg gather)
        for (int idx = t; idx < 64 * 32; idx += 256) {
            int r = idx >> 5, c4 = idx & 31;
            int gr = row0 + r;
            if (gr < nrows) {
                float4 v = *(const float4*)&sm.Cs[r][c4 * 4];
                __half2 h0 = __floats2half2_rn(v.x, v.y);
                __half2 h1 = __floats2half2_rn(v.z, v.w);
                uint2 u;
                u.x = *(unsigned int*)&h0;
                u.y = *(unsigned int*)&h1;
                ((uint2*)Ch)[(size_t)gr * 32 + c4] = u;
            }
        }
        {
            int row = t >> 2, h = t & 3;
            int gr = row0 + row;
            if (gr < nrows) {
                const float* cr = &sm.Cs[row][h * 32];
                float s = 0.f, d = 0.f;
#pragma unroll
                for (int c = 0; c < 32; c++) {
                    float v = cr[c];
                    s = fmaf(v, asrc[h * 32 + c], s);
                    d = fmaf(v, adst[h * 32 + c], d);
                }
                pas[(size_t)gr * 4 + h] = s;
                pad[(size_t)gr * 4 + h] = d;
            }
        }
    } else {
        for (int idx = t; idx < 64 * 32; idx += 256) {
            int r = idx >> 5, c4 = idx & 31;
            int gr = row0 + r;
            if (gr < nrows) {
                float4 v = *(const float4*)&sm.Cs[r][c4 * 4];
                if (bias) {
                    float4 bb = ((const float4*)bias)[c4];
                    v.x += bb.x; v.y += bb.y; v.z += bb.z; v.w += bb.w;
                }
                if (RELU) {
                    v.x = fmaxf(v.x, 0.f); v.y = fmaxf(v.y, 0.f);
                    v.z = fmaxf(v.z, 0.f); v.w = fmaxf(v.w, 0.f);
                }
                ((float4*)C)[(size_t)gr * 32 + c4] = v;
            }
        }
    }
}

// CSR-ordered alpha: thread p handles CSR slot p, stores exp(leaky_relu(...)).
__global__ void alpha_k(const float* __restrict__ ea, int layer) {
    __shared__ float sM[64];
    __shared__ float sloop[4];
    int t = threadIdx.x;
    if (t < 64) sM[t] = g_M2[layer][t];
    if (t < 4) sloop[t] = g_aeloop2[layer][t];
    __syncthreads();
    int p = blockIdx.x * blockDim.x + t;
    if (p >= E2) return;
    int eid = g_csr[p];
    int src = g_csrsrc[p];
    int dst = g_csrdst[p];
    float a0, a1, a2, a3;
    if (eid < EE) {
        a0 = a1 = a2 = a3 = 0.f;
        const float* er = ea + (size_t)eid * 16;
#pragma unroll
        for (int k = 0; k < 16; k++) {
            float v = er[k];
            a0 += v * sM[k * 4 + 0]; a1 += v * sM[k * 4 + 1];
            a2 += v * sM[k * 4 + 2]; a3 += v * sM[k * 4 + 3];
        }
    } else {
        a0 = sloop[0]; a1 = sloop[1]; a2 = sloop[2]; a3 = sloop[3];
    }
    float4 as4 = ((const float4*)g_as)[src];
    float4 ad4 = ((const float4*)g_ad)[dst];
    float v0 = as4.x + ad4.x + a0, v1 = as4.y + ad4.y + a1;
    float v2 = as4.z + ad4.z + a2, v3 = as4.w + ad4.w + a3;
    v0 = v0 > 0.f ? v0 : 0.2f * v0;
    v1 = v1 > 0.f ? v1 : 0.2f * v1;
    v2 = v2 > 0.f ? v2 : 0.2f * v2;
    v3 = v3 > 0.f ? v3 : 0.2f * v3;
    ((float4*)g_alpha)[p] = make_float4(__expf(v0), __expf(v1), __expf(v2), __expf(v3));
}

__device__ __forceinline__ float hsel(float4 a, int h) {
    return (h == 0) ? a.x : (h == 1) ? a.y : (h == 2) ? a.z : a.w;
}

// warp per dst node: sequential exp-alpha, fp16 xs gather (8B/lane/edge),
// fp32 accumulate + bias + LN + ELU fused.
__global__ void nodeagg_k(const float* __restrict__ bias,
                          const float* __restrict__ gamma,
                          const float* __restrict__ beta) {
    int n = (blockIdx.x * blockDim.x + threadIdx.x) >> 5;
    int lane = threadIdx.x & 31;
    if (n >= NN) return;
    int s0 = g_rowptr[n], e0 = g_rowptr[n + 1];
    s0 = iclamp(s0, 0, E2); e0 = iclamp(e0, s0, E2);
    const float4* A4 = (const float4*)g_alpha;
    const uint2* XH = (const uint2*)g_xsh;
    int h = lane >> 3;

    float den = 0.f;
    float4 acc = make_float4(0.f, 0.f, 0.f, 0.f);
    int i = s0;
    for (; i + 2 <= e0; i += 2) {
        float4 aA = A4[i];
        float4 aB = A4[i + 1];
        int sA = g_csrsrc[i], sB = g_csrsrc[i + 1];
        uint2 uA = XH[(size_t)sA * 32 + lane];
        uint2 uB = XH[(size_t)sB * 32 + lane];
        float exA = hsel(aA, h);
        float exB = hsel(aB, h);
        den += exA + exB;
        float2 fA0 = __half22float2(*(__half2*)&uA.x);
        float2 fA1 = __half22float2(*(__half2*)&uA.y);
        float2 fB0 = __half22float2(*(__half2*)&uB.x);
        float2 fB1 = __half22float2(*(__half2*)&uB.y);
        acc.x = fmaf(fA0.x, exA, fmaf(fB0.x, exB, acc.x));
        acc.y = fmaf(fA0.y, exA, fmaf(fB0.y, exB, acc.y));
        acc.z = fmaf(fA1.x, exA, fmaf(fB1.x, exB, acc.z));
        acc.w = fmaf(fA1.y, exA, fmaf(fB1.y, exB, acc.w));
    }
    if (i < e0) {
        float4 aA = A4[i];
        int sA = g_csrsrc[i];
        uint2 uA = XH[(size_t)sA * 32 + lane];
        float exA = hsel(aA, h);
        den += exA;
        float2 fA0 = __half22float2(*(__half2*)&uA.x);
        float2 fA1 = __half22float2(*(__half2*)&uA.y);
        acc.x = fmaf(fA0.x, exA, acc.x); acc.y = fmaf(fA0.y, exA, acc.y);
        acc.z = fmaf(fA1.x, exA, acc.z); acc.w = fmaf(fA1.y, exA, acc.w);
    }
    float inv = 1.f / (den + 1e-16f);
    acc.x *= inv; acc.y *= inv; acc.z *= inv; acc.w *= inv;
    float4 bb = ((const float4*)bias)[lane];
    acc.x += bb.x; acc.y += bb.y; acc.z += bb.z; acc.w += bb.w;

    float ssum = wredsum(acc.x + acc.y + acc.z + acc.w);
    float mean = ssum * (1.f / 128.f);
    float dx = acc.x - mean, dy = acc.y - mean, dz = acc.z - mean, dw = acc.w - mean;
    float q = wredsum(dx * dx + dy * dy + dz * dz + dw * dw);
    float rstd = rsqrtf(q * (1.f / 128.f) + 1e-5f);
    float4 gg = ((const float4*)gamma)[lane];
    float4 be = ((const float4*)beta)[lane];
    float r0 = dx * rstd * gg.x + be.x;
    float r1 = dy * rstd * gg.y + be.y;
    float r2 = dz * rstd * gg.z + be.z;
    float r3 = dw * rstd * gg.w + be.w;
    r0 = r0 > 0.f ? r0 : (__expf(r0) - 1.f);
    r1 = r1 > 0.f ? r1 : (__expf(r1) - 1.f);
    r2 = r2 > 0.f ? r2 : (__expf(r2) - 1.f);
    r3 = r3 > 0.f ? r3 : (__expf(r3) - 1.f);
    ((float4*)g_h)[(size_t)n * 32 + lane] = make_float4(r0, r1, r2, r3);
}

__global__ void gmean_k(float* __restrict__ gout) {
    int b = blockIdx.x >> 2, cg = blockIdx.x & 3;
    int t = threadIdx.x;
    int col = cg * 32 + (t & 31);
    int rg = t >> 5;  // 0..3
    int s = g_bstart[b], e = g_bstart[b + 1];
    float acc = 0.f;
    for (int n = s + rg; n < e; n += 4) acc += g_tmp[(size_t)n * EMB + col];
    __shared__ float sh[4][32];
    sh[rg][t & 31] = acc;
    __syncthreads();
    if (t < 32) {
        float v = sh[0][t] + sh[1][t] + sh[2][t] + sh[3][t];
        float cnt = (float)(e - s);
        gout[b * EMB + cg * 32 + t] = v / fmaxf(cnt, 1.f);
    }
}

// ---------------- launch ----------------
#define CK(name) do { cudaError_t _e = cudaPeekAtLastError(); \
    if (_e != cudaSuccess) { \
        fprintf(stderr, "LAUNCHFAIL %s: %s\n", name, cudaGetErrorString(_e)); \
        fflush(stderr); exit(3); } } while (0)

extern "C" void kernel_launch(void* const* d_in, const int* in_sizes, int n_in,
                              void* d_out, int out_size) {
    static const int SIG[22] = {1600000, 12800000, 4096, 128, 40960, 4096, 256, 256, 256,
                                256, 256, 256, 16384, 128, 128, 128, 16384, 128, 128, 128,
                                1600000, 50000};
    bool sig_ok = (n_in == 22);
    if (sig_ok) for (int i = 0; i < 22; i++) if (in_sizes[i] != SIG[i]) sig_ok = false;
    if (!sig_ok) {
        fprintf(stderr, "SIZEDUMP n_in=%d out_size=%d sizes:", n_in, out_size);
        for (int i = 0; i < n_in; i++) fprintf(stderr, " %d", in_sizes[i]);
        fprintf(stderr, "\n"); fflush(stderr);
        exit(2);
    }

    const float* x            = (const float*)d_in[0];
    const float* edge_attr    = (const float*)d_in[1];
    const float* W_in         = (const float*)d_in[2];
    const float* b_in         = (const float*)d_in[3];
    const float* W_src        = (const float*)d_in[4];
    const float* W_edge       = (const float*)d_in[5];
    const float* att_src      = (const float*)d_in[6];
    const float* att_dst      = (const float*)d_in[7];
    const float* att_edge     = (const float*)d_in[8];
    const float* gat_bias     = (const float*)d_in[9];
    const float* ln_gamma     = (const float*)d_in[10];
    const float* ln_beta      = (const float*)d_in[11];
    const float* W_out        = (const float*)d_in[12];
    const float* b_out        = (const float*)d_in[13];
    const float* ln_out_gamma = (const float*)d_in[14];
    const float* ln_out_beta  = (const float*)d_in[15];
    const float* W_g          = (const float*)d_in[16];
    const float* b_g          = (const float*)d_in[17];
    const float* gg_gamma     = (const float*)d_in[18];
    const float* gg_beta      = (const float*)d_in[19];
    const int*   ei           = (const int*)d_in[20];
    const int*   batch        = (const int*)d_in[21];
    float* out = (float*)d_out;

    // resolve device-symbol addresses on the host (R6 root-cause fix)
    float *p_h = nullptr, *p_tmp = nullptr, *p_as = nullptr, *p_ad = nullptr;
    unsigned int* p_xsh = nullptr;
    if (cudaGetSymbolAddress((void**)&p_h,  g_h)  != cudaSuccess ||
        cudaGetSymbolAddress((void**)&p_xsh, g_xsh) != cudaSuccess ||
        cudaGetSymbolAddress((void**)&p_tmp, g_tmp) != cudaSuccess ||
        cudaGetSymbolAddress((void**)&p_as, g_as) != cudaSuccess ||
        cudaGetSymbolAddress((void**)&p_ad, g_ad) != cudaSuccess) {
        fprintf(stderr, "SYMADDR failed\n"); fflush(stderr); exit(3);
    }

    const int GEMM_GRID = (NN + 63) / 64;   // BM=64 (R12/R14 tile)

    // order keeps the big K=160 src-GEMM as the 4th launch (ncu sample slot)
    setup_a_k<<<128 + (NN + 255) / 256, 256>>>(edge_attr);             CK("setup_a");
    setup_b_k<<<1 + (NN + 255) / 256, 256>>>(W_edge, att_edge, batch); CK("setup_b");
    gemmtc_k<32, 0, true, 0><<<GEMM_GRID, 256>>>(
        x, nullptr, W_in, b_in, p_h, NN,
        nullptr, nullptr, nullptr, nullptr, nullptr, nullptr, nullptr); CK("gemm_in");
    gemmtc_k<32, 128, false, 1><<<GEMM_GRID, 256>>>(
        x, p_h, W_src, nullptr, nullptr, NN,
        att_src, att_dst, p_as, p_ad, nullptr, nullptr, p_xsh);        CK("gemm_src0");
    hist_k<<<(E2 + 255) / 256, 256>>>(ei);                             CK("hist");
    scan_k<<<1, 1024>>>();                                             CK("scan");
    scatter_k<<<(E2 + 255) / 256, 256>>>(ei);                          CK("scatter");

    alpha_k<<<(E2 + 255) / 256, 256>>>(edge_attr, 0);                  CK("alpha0");
    nodeagg_k<<<(NN * 32 + 255) / 256, 256>>>(gat_bias, ln_gamma, ln_beta);
    CK("nodeagg0");

    gemmtc_k<32, 128, false, 1><<<GEMM_GRID, 256>>>(
        x, p_h, W_src + 160 * EMB, nullptr, nullptr, NN,
        att_src + EMB, att_dst + EMB, p_as, p_ad, nullptr, nullptr, p_xsh);
    CK("gemm_src1");
    alpha_k<<<(E2 + 255) / 256, 256>>>(edge_attr, 1);                  CK("alpha1");
    nodeagg_k<<<(NN * 32 + 255) / 256, 256>>>(gat_bias + EMB, ln_gamma + EMB,
                                              ln_beta + EMB);          CK("nodeagg1");

    gemmtc_k<128, 0, true, 2><<<GEMM_GRID, 256>>>(
        p_h, nullptr, W_out, b_out, out, NN,
        nullptr, nullptr, nullptr, nullptr, ln_out_gamma, ln_out_beta, nullptr);
    CK("gemm_out");

    gemmtc_k<128, 0, true, 2><<<GEMM_GRID, 256>>>(
        p_h, nullptr, W_g, b_g, p_tmp, NN,
        nullptr, nullptr, nullptr, nullptr, gg_gamma, gg_beta, nullptr);
    CK("gemm_g");
    gmean_k<<<BB * 4, 128>>>(out + (size_t)NN * EMB);                  CK("gmean");

    // ---- sentinel validation: ONLY on non-capture calls ----
    cudaStreamCaptureStatus cst = cudaStreamCaptureStatusNone;
    cudaError_t qe = cudaStreamIsCapturing(0, &cst);
    bool capturing = (qe != cudaSuccess) || (cst != cudaStreamCaptureStatusNone);
    if (!capturing) {
        cudaError_t se = cudaDeviceSynchronize();
        if (se != cudaSuccess) {
            fprintf(stderr, "SYNCFAIL: %s\n", cudaGetErrorString(se));
            fflush(stderr); exit(3);
        }
        int rowN = -1;
        float o0[4] = {0}, om[4] = {0}, og[4] = {0};
        cudaMemcpyFromSymbol(&rowN, g_rowptr, sizeof(int), sizeof(int) * NN);
        cudaMemcpy(o0, out, sizeof(o0), cudaMemcpyDeviceToHost);
        cudaMemcpy(om, out + (size_t)25000 * 128, sizeof(om), cudaMemcpyDeviceToHost);
        cudaMemcpy(og, out + (size_t)NN * 128, sizeof(og), cudaMemcpyDeviceToHost);

        float mag = 0.f;
        for (int i = 0; i < 4; i++) mag += fabsf(o0[i]) + fabsf(om[i]);
        bool bad = (rowN != E2) || (mag < 1e-9f);
        for (int i = 0; i < 4; i++)
            if (!std::isfinite(o0[i]) || !std::isfinite(om[i]) || !std::isfinite(og[i]))
                bad = true;
        if (bad) {
            fprintf(stderr,
                "SENTINEL rowN=%d out0=%.6g,%.6g,%.6g,%.6g outM=%.6g,%.6g outG=%.6g,%.6g\n",
                rowN, o0[0], o0[1], o0[2], o0[3], om[0], om[1], og[0], og[1]);
            fflush(stderr);
            exit(3);
        }
    }
}

// round 17
// speedup vs baseline: 1.4648x; 1.4648x over previous
#include <cuda_runtime.h>
#include <cuda_fp16.h>
#include <mma.h>
#include <cstdio>
#include <cstdlib>
#include <cmath>

using namespace nvcuda;

#define NN 50000
#define EE 800000
#define E2 850000   // EE + NN self loops
#define EMB 128
#define LL 2
#define BB 8

// ---------------- scratch (no cudaMalloc allowed) ----------------
// NOTE: host code must NEVER pass these symbols as kernel args directly —
// always cudaGetSymbolAddress (R6 root cause).
__device__ __align__(16) float g_h[NN * EMB];
__device__ __align__(16) unsigned int g_xsh[NN * 64];     // xs as half2 pairs (only consumer: nodeagg)
__device__ __align__(16) float g_tmp[NN * EMB];
__device__ __align__(16) float g_as[NN * 4];
__device__ __align__(16) float g_ad[NN * 4];
__device__ __align__(16) float g_alpha[(size_t)E2 * 4];   // exp(alpha), CSR order
__device__ int   g_deg[NN];
__device__ int   g_rowptr[NN + 1];
__device__ int   g_wpos[NN];
__device__ int   g_csr[E2];
__device__ int   g_csrsrc[E2];
__device__ int   g_csrdst[E2];
__device__ float g_part[128 * 16];
__device__ float g_M2[LL][64];      // per-layer [16][4]
__device__ float g_aeloop2[LL][4];
__device__ int   g_bstart[BB + 1];

__device__ __forceinline__ float wredsum(float v) {
#pragma unroll
    for (int o = 16; o; o >>= 1) v += __shfl_xor_sync(0xffffffffu, v, o);
    return v;
}
__device__ __forceinline__ int iclamp(int v, int lo, int hi) {
    return v < lo ? lo : (v > hi ? hi : v);
}

// ---------------- setup_a: emean partials (blocks 0..127) + zero_deg (blocks 128+) ----
__global__ void setup_a_k(const float* __restrict__ ea) {
    if (blockIdx.x >= 128) {
        int i = (blockIdx.x - 128) * blockDim.x + threadIdx.x;
        if (i < NN) g_deg[i] = 0;
        return;
    }
    float acc[16];
#pragma unroll
    for (int k = 0; k < 16; k++) acc[k] = 0.f;
    for (int e = blockIdx.x * blockDim.x + threadIdx.x; e < EE; e += 128 * blockDim.x) {
        const float4* p = (const float4*)(ea + (size_t)e * 16);
#pragma unroll
        for (int q = 0; q < 4; q++) {
            float4 v = p[q];
            acc[q * 4 + 0] += v.x; acc[q * 4 + 1] += v.y;
            acc[q * 4 + 2] += v.z; acc[q * 4 + 3] += v.w;
        }
    }
    __shared__ float sh[256 * 16];
    int t = threadIdx.x;
#pragma unroll
    for (int k = 0; k < 16; k++) sh[t * 16 + k] = acc[k];
    __syncthreads();
    for (int off = 128; off; off >>= 1) {
        if (t < off)
#pragma unroll
            for (int k = 0; k < 16; k++) sh[t * 16 + k] += sh[(t + off) * 16 + k];
        __syncthreads();
    }
    if (t < 16) g_part[blockIdx.x * 16 + t] = sh[t];
}

// ---------------- setup_b: block 0 = emean2 + prepM(both layers); blocks 1+ = bounds --
__global__ void setup_b_k(const float* __restrict__ W_edge,
                          const float* __restrict__ att_edge,
                          const int* __restrict__ batch) {
    if (blockIdx.x > 0) {
        int n = (blockIdx.x - 1) * blockDim.x + threadIdx.x;
        if (n >= NN) return;
        int b = iclamp(batch[n], 0, BB - 1);
        if (n == 0) {
            for (int bb = 0; bb <= b; bb++) g_bstart[bb] = 0;
        } else {
            int bp = iclamp(batch[n - 1], 0, BB - 1);
            for (int bb = bp + 1; bb <= b; bb++) g_bstart[bb] = n;
        }
        if (n == NN - 1) {
            for (int bb = b + 1; bb <= BB; bb++) g_bstart[bb] = NN;
        }
        return;
    }
    __shared__ float sem[16];
    __shared__ float sM[LL][64];
    int t = threadIdx.x;
    if (t < 16) {
        float s = 0.f;
        for (int b = 0; b < 128; b++) s += g_part[b * 16 + t];
        sem[t] = s * (1.f / (float)EE);
    }
    __syncthreads();
    if (t < 128) {
        int l = t >> 6, kk = (t & 63) >> 2, h = t & 3;
        const float* We = W_edge + l * 16 * EMB;
        const float* ae = att_edge + l * EMB;
        float s = 0.f;
#pragma unroll
        for (int c = 0; c < 32; c++) s += We[kk * 128 + h * 32 + c] * ae[h * 32 + c];
        sM[l][kk * 4 + h] = s;
        g_M2[l][kk * 4 + h] = s;
    }
    __syncthreads();
    if (t < 8) {
        int l = t >> 2, h = t & 3;
        float s = 0.f;
        for (int k = 0; k < 16; k++) s += sem[k] * sM[l][k * 4 + h];
        g_aeloop2[l][h] = s;
    }
}

__global__ void hist_k(const int* __restrict__ ei) {
    int e = blockIdx.x * blockDim.x + threadIdx.x;
    if (e >= E2) return;
    int dst = (e < EE) ? ei[EE + e] : (e - EE);
    dst = iclamp(dst, 0, NN - 1);
    atomicAdd(&g_deg[dst], 1);
}

__global__ void scan_k() {
    const int T = 1024;
    __shared__ int wsum[32];
    __shared__ int carry;
    int t = threadIdx.x, lane = t & 31, w = t >> 5;
    if (t == 0) carry = 0;
    __syncthreads();
    for (int base = 0; base < NN; base += T) {
        int i = base + t;
        int v = (i < NN) ? g_deg[i] : 0;
        int x = v;
#pragma unroll
        for (int o = 1; o < 32; o <<= 1) {
            int y = __shfl_up_sync(0xffffffffu, x, o);
            if (lane >= o) x += y;
        }
        if (lane == 31) wsum[w] = x;
        __syncthreads();
        if (w == 0) {
            int y = wsum[lane];
#pragma unroll
            for (int o = 1; o < 32; o <<= 1) {
                int z = __shfl_up_sync(0xffffffffu, y, o);
                if (lane >= o) y += z;
            }
            wsum[lane] = y;
        }
        __syncthreads();
        int pre = (w > 0) ? wsum[w - 1] : 0;
        int excl = carry + pre + x - v;
        if (i < NN) { g_rowptr[i] = excl; g_wpos[i] = excl; }
        int total = wsum[31];
        __syncthreads();
        if (t == 0) carry += total;
        __syncthreads();
    }
    if (t == 0) g_rowptr[NN] = carry;
}

__global__ void scatter_k(const int* __restrict__ ei) {
    int e = blockIdx.x * blockDim.x + threadIdx.x;
    if (e >= E2) return;
    int src, dst;
    if (e < EE) { src = ei[e]; dst = ei[EE + e]; }
    else        { src = dst = e - EE; }
    src = iclamp(src, 0, NN - 1);
    dst = iclamp(dst, 0, NN - 1);
    int p = atomicAdd(&g_wpos[dst], 1);
    p = iclamp(p, 0, E2 - 1);
    g_csr[p] = e;
    g_csrsrc[p] = src;
    g_csrdst[p] = dst;
}

// ---------------- TF32 tensor-core GEMM, BM=64, software-pipelined staging ----
// (R14 mainloop — validated 63.6us @ K=160; mainloop untouched)
// EPI: 0 = store fp32 (+bias/relu); 1 = store HALF2 to Ch + a_s/a_d dots;
//      2 = bias+relu+LayerNorm fp32
template <int K0, int K1, bool RELU, int EPI>
__global__ __launch_bounds__(256, 3) void gemmtc_k(
    const float* __restrict__ A0, const float* __restrict__ A1,
    const float* __restrict__ W, const float* __restrict__ bias,
    float* __restrict__ C, int nrows,
    const float* __restrict__ asrc, const float* __restrict__ adst,
    float* __restrict__ pas, float* __restrict__ pad,
    const float* __restrict__ gamma, const float* __restrict__ beta,
    unsigned int* __restrict__ Ch)
{
    constexpr int K = K0 + K1;
    constexpr int KC = 32;
    constexpr int NCH = (K + KC - 1) / KC;
    constexpr int ALD = KC + 8;    // 40
    constexpr int WLD = 128 + 8;   // 136
    constexpr int CLD = 128 + 4;   // 132

    __shared__ union {
        struct { float As[64][ALD]; float Ws[KC][WLD]; } L;
        float Cs[64][CLD];
    } sm;

    int t = threadIdx.x;
    int warp = t >> 5;
    int lane = t & 31;
    int wr = warp >> 1;   // 0..3
    int wc = warp & 1;    // 0..1
    int row0 = blockIdx.x * 64;

    int ra = t >> 5;         // A base row
    int ka = t & 31;         // A k-column
    int kw = t >> 7;         // W base k
    int jw = t & 127;        // W column

    float rAv[8];
    float rWv[16];

    wmma::fragment<wmma::accumulator, 16, 16, 8, float> acc[4];
#pragma unroll
    for (int j = 0; j < 4; j++) wmma::fill_fragment(acc[j], 0.f);

    {
        int gk = ka;
#pragma unroll
        for (int i = 0; i < 8; i++) {
            int gr = row0 + ra + i * 8;
            float v = 0.f;
            if (gr < nrows && gk < K) {
                if (K1 == 0 || gk < K0) v = A0[(size_t)gr * K0 + gk];
                else                    v = A1[(size_t)gr * K1 + (gk - K0)];
            }
            rAv[i] = v;
        }
#pragma unroll
        for (int i = 0; i < 16; i++) {
            int k = kw + i * 2;
            float v = (k < K) ? W[(size_t)k * 128 + jw] : 0.f;
            rWv[i] = v;
        }
    }

    for (int ch = 0; ch < NCH; ch++) {
#pragma unroll
        for (int i = 0; i < 8; i++)
            sm.L.As[ra + i * 8][ka] = wmma::__float_to_tf32(rAv[i]);
#pragma unroll
        for (int i = 0; i < 16; i++)
            sm.L.Ws[kw + i * 2][jw] = wmma::__float_to_tf32(rWv[i]);
        __syncthreads();

        if (ch + 1 < NCH) {
            int gkb = (ch + 1) * KC;
            int gk = gkb + ka;
#pragma unroll
            for (int i = 0; i < 8; i++) {
                int gr = row0 + ra + i * 8;
                float v = 0.f;
                if (gr < nrows && gk < K) {
                    if (K1 == 0 || gk < K0) v = A0[(size_t)gr * K0 + gk];
                    else                    v = A1[(size_t)gr * K1 + (gk - K0)];
                }
                rAv[i] = v;
            }
#pragma unroll
            for (int i = 0; i < 16; i++) {
                int k = gkb + kw + i * 2;
                float v = (k < K) ? W[(size_t)k * 128 + jw] : 0.f;
                rWv[i] = v;
            }
        }

#pragma unroll
        for (int ks = 0; ks < KC; ks += 8) {
            wmma::fragment<wmma::matrix_a, 16, 16, 8, wmma::precision::tf32,
                           wmma::row_major> fa;
            wmma::load_matrix_sync(fa, &sm.L.As[wr * 16][ks], ALD);
#pragma unroll
            for (int j = 0; j < 4; j++) {
                wmma::fragment<wmma::matrix_b, 16, 16, 8, wmma::precision::tf32,
                               wmma::row_major> fb;
                wmma::load_matrix_sync(fb, &sm.L.Ws[ks][wc * 64 + j * 16], WLD);
                wmma::mma_sync(acc[j], fa, fb, acc[j]);
            }
        }
        __syncthreads();
    }

#pragma unroll
    for (int j = 0; j < 4; j++)
        wmma::store_matrix_sync(&sm.Cs[wr * 16][wc * 64 + j * 16], acc[j], CLD,
                                wmma::mem_row_major);
    __syncthreads();

    if (EPI == 2) {
#pragma unroll 1
        for (int rr = 0; rr < 8; rr++) {
            int row = warp * 8 + rr;
            int gr = row0 + row;
            if (gr >= nrows) continue;
            float4 v = *(const float4*)&sm.Cs[row][lane * 4];
            float4 bb = ((const float4*)bias)[lane];
            v.x += bb.x; v.y += bb.y; v.z += bb.z; v.w += bb.w;
            if (RELU) {
                v.x = fmaxf(v.x, 0.f); v.y = fmaxf(v.y, 0.f);
                v.z = fmaxf(v.z, 0.f); v.w = fmaxf(v.w, 0.f);
            }
            float s = wredsum(v.x + v.y + v.z + v.w);
            float mean = s * (1.f / 128.f);
            float dx = v.x - mean, dy = v.y - mean, dz = v.z - mean, dw = v.w - mean;
            float q = wredsum(dx * dx + dy * dy + dz * dz + dw * dw);
            float rstd = rsqrtf(q * (1.f / 128.f) + 1e-5f);
            float4 gg = ((const float4*)gamma)[lane];
            float4 be = ((const float4*)beta)[lane];
            float4 r;
            r.x = dx * rstd * gg.x + be.x;
            r.y = dy * rstd * gg.y + be.y;
            r.z = dz * rstd * gg.z + be.z;
            r.w = dw * rstd * gg.w + be.w;
            ((float4*)C)[(size_t)gr * 32 + lane] = r;
        }
    } else if (EPI == 1) {
        // store xs as half2 pairs only (sole consumer: nodeagg gather)
        for (int idx = t; idx < 64 * 32; idx += 256) {
            int r = idx >> 5, c4 = idx & 31;
            int gr = row0 + r;
            if (gr < nrows) {
                float4 v = *(const float4*)&sm.Cs[r][c4 * 4];
                __half2 h0 = __floats2half2_rn(v.x, v.y);
                __half2 h1 = __floats2half2_rn(v.z, v.w);
                uint2 u;
                u.x = *(unsigned int*)&h0;
                u.y = *(unsigned int*)&h1;
                ((uint2*)Ch)[(size_t)gr * 32 + c4] = u;
            }
        }
        {
            int row = t >> 2, h = t & 3;
            int gr = row0 + row;
            if (gr < nrows) {
                const float* cr = &sm.Cs[row][h * 32];
                float s = 0.f, d = 0.f;
#pragma unroll
                for (int c = 0; c < 32; c++) {
                    float v = cr[c];
                    s = fmaf(v, asrc[h * 32 + c], s);
                    d = fmaf(v, adst[h * 32 + c], d);
                }
                pas[(size_t)gr * 4 + h] = s;
                pad[(size_t)gr * 4 + h] = d;
            }
        }
    } else {
        for (int idx = t; idx < 64 * 32; idx += 256) {
            int r = idx >> 5, c4 = idx & 31;
            int gr = row0 + r;
            if (gr < nrows) {
                float4 v = *(const float4*)&sm.Cs[r][c4 * 4];
                if (bias) {
                    float4 bb = ((const float4*)bias)[c4];
                    v.x += bb.x; v.y += bb.y; v.z += bb.z; v.w += bb.w;
                }
                if (RELU) {
                    v.x = fmaxf(v.x, 0.f); v.y = fmaxf(v.y, 0.f);
                    v.z = fmaxf(v.z, 0.f); v.w = fmaxf(v.w, 0.f);
                }
                ((float4*)C)[(size_t)gr * 32 + c4] = v;
            }
        }
    }
}

// CSR-ordered alpha: thread p handles CSR slot p, stores exp(leaky_relu(...)).
__global__ void alpha_k(const float* __restrict__ ea, int layer) {
    __shared__ float sM[64];
    __shared__ float sloop[4];
    int t = threadIdx.x;
    if (t < 64) sM[t] = g_M2[layer][t];
    if (t < 4) sloop[t] = g_aeloop2[layer][t];
    __syncthreads();
    int p = blockIdx.x * blockDim.x + t;
    if (p >= E2) return;
    int eid = g_csr[p];
    int src = g_csrsrc[p];
    int dst = g_csrdst[p];
    float a0, a1, a2, a3;
    if (eid < EE) {
        a0 = a1 = a2 = a3 = 0.f;
        const float* er = ea + (size_t)eid * 16;
#pragma unroll
        for (int k = 0; k < 16; k++) {
            float v = er[k];
            a0 += v * sM[k * 4 + 0]; a1 += v * sM[k * 4 + 1];
            a2 += v * sM[k * 4 + 2]; a3 += v * sM[k * 4 + 3];
        }
    } else {
        a0 = sloop[0]; a1 = sloop[1]; a2 = sloop[2]; a3 = sloop[3];
    }
    float4 as4 = ((const float4*)g_as)[src];
    float4 ad4 = ((const float4*)g_ad)[dst];
    float v0 = as4.x + ad4.x + a0, v1 = as4.y + ad4.y + a1;
    float v2 = as4.z + ad4.z + a2, v3 = as4.w + ad4.w + a3;
    v0 = v0 > 0.f ? v0 : 0.2f * v0;
    v1 = v1 > 0.f ? v1 : 0.2f * v1;
    v2 = v2 > 0.f ? v2 : 0.2f * v2;
    v3 = v3 > 0.f ? v3 : 0.2f * v3;
    ((float4*)g_alpha)[p] = make_float4(__expf(v0), __expf(v1), __expf(v2), __expf(v3));
}

__device__ __forceinline__ float hsel(float4 a, int h) {
    return (h == 0) ? a.x : (h == 1) ? a.y : (h == 2) ? a.z : a.w;
}

// warp per dst node: sequential exp-alpha, fp16 xs gather (8B/lane/edge),
// fp32 accumulate + bias + LN + ELU fused.
__global__ void nodeagg_k(const float* __restrict__ bias,
                          const float* __restrict__ gamma,
                          const float* __restrict__ beta) {
    int n = (blockIdx.x * blockDim.x + threadIdx.x) >> 5;
    int lane = threadIdx.x & 31;
    if (n >= NN) return;
    int s0 = g_rowptr[n], e0 = g_rowptr[n + 1];
    s0 = iclamp(s0, 0, E2); e0 = iclamp(e0, s0, E2);
    const float4* A4 = (const float4*)g_alpha;
    const uint2* XH = (const uint2*)g_xsh;
    int h = lane >> 3;

    float den = 0.f;
    float4 acc = make_float4(0.f, 0.f, 0.f, 0.f);
    int i = s0;
    for (; i + 2 <= e0; i += 2) {
        float4 aA = A4[i];
        float4 aB = A4[i + 1];
        int sA = g_csrsrc[i], sB = g_csrsrc[i + 1];
        uint2 uA = XH[(size_t)sA * 32 + lane];
        uint2 uB = XH[(size_t)sB * 32 + lane];
        float exA = hsel(aA, h);
        float exB = hsel(aB, h);
        den += exA + exB;
        float2 fA0 = __half22float2(*(__half2*)&uA.x);
        float2 fA1 = __half22float2(*(__half2*)&uA.y);
        float2 fB0 = __half22float2(*(__half2*)&uB.x);
        float2 fB1 = __half22float2(*(__half2*)&uB.y);
        acc.x = fmaf(fA0.x, exA, fmaf(fB0.x, exB, acc.x));
        acc.y = fmaf(fA0.y, exA, fmaf(fB0.y, exB, acc.y));
        acc.z = fmaf(fA1.x, exA, fmaf(fB1.x, exB, acc.z));
        acc.w = fmaf(fA1.y, exA, fmaf(fB1.y, exB, acc.w));
    }
    if (i < e0) {
        float4 aA = A4[i];
        int sA = g_csrsrc[i];
        uint2 uA = XH[(size_t)sA * 32 + lane];
        float exA = hsel(aA, h);
        den += exA;
        float2 fA0 = __half22float2(*(__half2*)&uA.x);
        float2 fA1 = __half22float2(*(__half2*)&uA.y);
        acc.x = fmaf(fA0.x, exA, acc.x); acc.y = fmaf(fA0.y, exA, acc.y);
        acc.z = fmaf(fA1.x, exA, acc.z); acc.w = fmaf(fA1.y, exA, acc.w);
    }
    float inv = 1.f / (den + 1e-16f);
    acc.x *= inv; acc.y *= inv; acc.z *= inv; acc.w *= inv;
    float4 bb = ((const float4*)bias)[lane];
    acc.x += bb.x; acc.y += bb.y; acc.z += bb.z; acc.w += bb.w;

    float ssum = wredsum(acc.x + acc.y + acc.z + acc.w);
    float mean = ssum * (1.f / 128.f);
    float dx = acc.x - mean, dy = acc.y - mean, dz = acc.z - mean, dw = acc.w - mean;
    float q = wredsum(dx * dx + dy * dy + dz * dz + dw * dw);
    float rstd = rsqrtf(q * (1.f / 128.f) + 1e-5f);
    float4 gg = ((const float4*)gamma)[lane];
    float4 be = ((const float4*)beta)[lane];
    float r0 = dx * rstd * gg.x + be.x;
    float r1 = dy * rstd * gg.y + be.y;
    float r2 = dz * rstd * gg.z + be.z;
    float r3 = dw * rstd * gg.w + be.w;
    r0 = r0 > 0.f ? r0 : (__expf(r0) - 1.f);
    r1 = r1 > 0.f ? r1 : (__expf(r1) - 1.f);
    r2 = r2 > 0.f ? r2 : (__expf(r2) - 1.f);
    r3 = r3 > 0.f ? r3 : (__expf(r3) - 1.f);
    ((float4*)g_h)[(size_t)n * 32 + lane] = make_float4(r0, r1, r2, r3);
}

__global__ void gmean_k(float* __restrict__ gout) {
    int b = blockIdx.x >> 2, cg = blockIdx.x & 3;
    int t = threadIdx.x;
    int col = cg * 32 + (t & 31);
    int rg = t >> 5;  // 0..3
    int s = g_bstart[b], e = g_bstart[b + 1];
    float acc = 0.f;
    for (int n = s + rg; n < e; n += 4) acc += g_tmp[(size_t)n * EMB + col];
    __shared__ float sh[4][32];
    sh[rg][t & 31] = acc;
    __syncthreads();
    if (t < 32) {
        float v = sh[0][t] + sh[1][t] + sh[2][t] + sh[3][t];
        float cnt = (float)(e - s);
        gout[b * EMB + cg * 32 + t] = v / fmaxf(cnt, 1.f);
    }
}

// ---------------- launch ----------------
#define CK(name) do { cudaError_t _e = cudaPeekAtLastError(); \
    if (_e != cudaSuccess) { \
        fprintf(stderr, "LAUNCHFAIL %s: %s\n", name, cudaGetErrorString(_e)); \
        fflush(stderr); exit(3); } } while (0)

extern "C" void kernel_launch(void* const* d_in, const int* in_sizes, int n_in,
                              void* d_out, int out_size) {
    static const int SIG[22] = {1600000, 12800000, 4096, 128, 40960, 4096, 256, 256, 256,
                                256, 256, 256, 16384, 128, 128, 128, 16384, 128, 128, 128,
                                1600000, 50000};
    bool sig_ok = (n_in == 22);
    if (sig_ok) for (int i = 0; i < 22; i++) if (in_sizes[i] != SIG[i]) sig_ok = false;
    if (!sig_ok) {
        fprintf(stderr, "SIZEDUMP n_in=%d out_size=%d sizes:", n_in, out_size);
        for (int i = 0; i < n_in; i++) fprintf(stderr, " %d", in_sizes[i]);
        fprintf(stderr, "\n"); fflush(stderr);
        exit(2);
    }

    const float* x            = (const float*)d_in[0];
    const float* edge_attr    = (const float*)d_in[1];
    const float* W_in         = (const float*)d_in[2];
    const float* b_in         = (const float*)d_in[3];
    const float* W_src        = (const float*)d_in[4];
    const float* W_edge       = (const float*)d_in[5];
    const float* att_src      = (const float*)d_in[6];
    const float* att_dst      = (const float*)d_in[7];
    const float* att_edge     = (const float*)d_in[8];
    const float* gat_bias     = (const float*)d_in[9];
    const float* ln_gamma     = (const float*)d_in[10];
    const float* ln_beta      = (const float*)d_in[11];
    const float* W_out        = (const float*)d_in[12];
    const float* b_out        = (const float*)d_in[13];
    const float* ln_out_gamma = (const float*)d_in[14];
    const float* ln_out_beta  = (const float*)d_in[15];
    const float* W_g          = (const float*)d_in[16];
    const float* b_g          = (const float*)d_in[17];
    const float* gg_gamma     = (const float*)d_in[18];
    const float* gg_beta      = (const float*)d_in[19];
    const int*   ei           = (const int*)d_in[20];
    const int*   batch        = (const int*)d_in[21];
    float* out = (float*)d_out;

    // resolve device-symbol addresses on the host (R6 root-cause fix)
    float *p_h = nullptr, *p_tmp = nullptr, *p_as = nullptr, *p_ad = nullptr;
    unsigned int* p_xsh = nullptr;
    if (cudaGetSymbolAddress((void**)&p_h,  g_h)  != cudaSuccess ||
        cudaGetSymbolAddress((void**)&p_xsh, g_xsh) != cudaSuccess ||
        cudaGetSymbolAddress((void**)&p_tmp, g_tmp) != cudaSuccess ||
        cudaGetSymbolAddress((void**)&p_as, g_as) != cudaSuccess ||
        cudaGetSymbolAddress((void**)&p_ad, g_ad) != cudaSuccess) {
        fprintf(stderr, "SYMADDR failed\n"); fflush(stderr); exit(3);
    }

    const int GEMM_GRID = (NN + 63) / 64;   // BM=64 (R12/R14 tile)

    // order keeps the big K=160 src-GEMM as the 4th launch (ncu sample slot)
    setup_a_k<<<128 + (NN + 255) / 256, 256>>>(edge_attr);             CK("setup_a");
    setup_b_k<<<1 + (NN + 255) / 256, 256>>>(W_edge, att_edge, batch); CK("setup_b");
    gemmtc_k<32, 0, true, 0><<<GEMM_GRID, 256>>>(
        x, nullptr, W_in, b_in, p_h, NN,
        nullptr, nullptr, nullptr, nullptr, nullptr, nullptr, nullptr); CK("gemm_in");
    gemmtc_k<32, 128, false, 1><<<GEMM_GRID, 256>>>(
        x, p_h, W_src, nullptr, nullptr, NN,
        att_src, att_dst, p_as, p_ad, nullptr, nullptr, p_xsh);        CK("gemm_src0");
    hist_k<<<(E2 + 255) / 256, 256>>>(ei);                             CK("hist");
    scan_k<<<1, 1024>>>();                                             CK("scan");
    scatter_k<<<(E2 + 255) / 256, 256>>>(ei);                          CK("scatter");

    alpha_k<<<(E2 + 255) / 256, 256>>>(edge_attr, 0);                  CK("alpha0");
    nodeagg_k<<<(NN * 32 + 255) / 256, 256>>>(gat_bias, ln_gamma, ln_beta);
    CK("nodeagg0");

    gemmtc_k<32, 128, false, 1><<<GEMM_GRID, 256>>>(
        x, p_h, W_src + 160 * EMB, nullptr, nullptr, NN,
        att_src + EMB, att_dst + EMB, p_as, p_ad, nullptr, nullptr, p_xsh);
    CK("gemm_src1");
    alpha_k<<<(E2 + 255) / 256, 256>>>(edge_attr, 1);                  CK("alpha1");
    nodeagg_k<<<(NN * 32 + 255) / 256, 256>>>(gat_bias + EMB, ln_gamma + EMB,
                                              ln_beta + EMB);          CK("nodeagg1");

    gemmtc_k<128, 0, true, 2><<<GEMM_GRID, 256>>>(
        p_h, nullptr, W_out, b_out, out, NN,
        nullptr, nullptr, nullptr, nullptr, ln_out_gamma, ln_out_beta, nullptr);
    CK("gemm_out");

    gemmtc_k<128, 0, true, 2><<<GEMM_GRID, 256>>>(
        p_h, nullptr, W_g, b_g, p_tmp, NN,
        nullptr, nullptr, nullptr, nullptr, gg_gamma, gg_beta, nullptr);
    CK("gemm_g");
    gmean_k<<<BB * 4, 128>>>(out + (size_t)NN * EMB);                  CK("gmean");

    // ---- sentinel validation: ONLY on non-capture calls ----
    cudaStreamCaptureStatus cst = cudaStreamCaptureStatusNone;
    cudaError_t qe = cudaStreamIsCapturing(0, &cst);
    bool capturing = (qe != cudaSuccess) || (cst != cudaStreamCaptureStatusNone);
    if (!capturing) {
        cudaError_t se = cudaDeviceSynchronize();
        if (se != cudaSuccess) {
            fprintf(stderr, "SYNCFAIL: %s\n", cudaGetErrorString(se));
            fflush(stderr); exit(3);
        }
        int rowN = -1;
        float o0[4] = {0}, om[4] = {0}, og[4] = {0};
        cudaMemcpyFromSymbol(&rowN, g_rowptr, sizeof(int), sizeof(int) * NN);
        cudaMemcpy(o0, out, sizeof(o0), cudaMemcpyDeviceToHost);
        cudaMemcpy(om, out + (size_t)25000 * 128, sizeof(om), cudaMemcpyDeviceToHost);
        cudaMemcpy(og, out + (size_t)NN * 128, sizeof(og), cudaMemcpyDeviceToHost);

        float mag = 0.f;
        for (int i = 0; i < 4; i++) mag += fabsf(o0[i]) + fabsf(om[i]);
        bool bad = (rowN != E2) || (mag < 1e-9f);
        for (int i = 0; i < 4; i++)
            if (!std::isfinite(o0[i]) || !std::isfinite(om[i]) || !std::isfinite(og[i]))
                bad = true;
        if (bad) {
            fprintf(stderr,
                "SENTINEL rowN=%d out0=%.6g,%.6g,%.6g,%.6g outM=%.6g,%.6g outG=%.6g,%.6g\n",
                rowN, o0[0], o0[1], o0[2], o0[3], om[0], om[1], og[0], og[1]);
            fflush(stderr);
            exit(3);
        }
    }
}